// round 15
// baseline (speedup 1.0000x reference)
#include <cuda_runtime.h>
#include <cuda_fp16.h>
#include <mma.h>

using namespace nvcuda;

// Problem constants (fixed by reference)
#define NN    50000
#define NE    800000
#define FDIM  128
#define CAP   64                          // padded CSR row capacity (Poisson(16))

#define EPT   8
#define NEDGT (NE / EPT)                  // 100000 edge-threads

#define NCHUNK 4
#define CHUNK  (98 * 128)                 // 12544 nodes per chunk (tile aligned)

typedef unsigned long long ull;

// smem layout for the TC GEMM (128-row tiles)
#define BM        128
#define AH_BYTES  (BM * 136 * 2)            // 34816
#define WH_BYTES  (128 * 136 * 2)           // 34816
#define GEMM_SMEM (AH_BYTES + WH_BYTES)     // 69632
#define CS_PITCH  132

// ---------------- scratch (device globals; no runtime allocation) ----------
__device__ __half g_h16a[NN * FDIM];       // layer-1 fp16 gather table
__device__ __half g_h16b[NN * FDIM];       // layer-2 fp16 gather table
__device__ __half g_feat16[NN * FDIM];     // layer-1 output (fp16, GEMM2 input)
__device__ float4 g_AS1[NN], g_AD1[NN];    // layer-1 alphas
__device__ float4 g_AS2[NN], g_AD2[NN];    // layer-2 alphas
__device__ int    g_cnt[NN];               // zero at entry; agg_final re-zeros
__device__ int    g_csrc[NN * CAP];        // padded CSR (12.8 MB)
__device__ float  g_weff[FDIM];
__device__ float  g_beff;

// ---------------- packed f32x2 helpers ----------------
__device__ __forceinline__ ull pk2(float v) {
    ull r; asm("mov.b64 %0, {%1, %1};" : "=l"(r) : "f"(v)); return r;
}
__device__ __forceinline__ void ffma2(ull& d, ull a, ull b) {
    asm("fma.rn.f32x2 %0, %1, %2, %0;" : "+l"(d) : "l"(a), "l"(b));
}
__device__ __forceinline__ float2 up2(ull r) {
    float2 f; asm("mov.b64 {%0, %1}, %2;" : "=f"(f.x), "=f"(f.y) : "l"(r)); return f;
}
__device__ __forceinline__ ull h2pair(unsigned u) {
    __half2 hh = *(__half2*)&u;
    float2 f = __half22float2(hh);
    ull p; asm("mov.b64 %0, {%1, %2};" : "=l"(p) : "f"(f.x), "f"(f.y));
    return p;
}

// ---------------- padded-CSR build: ONE pass, no scan, no barriers --------
__global__ void csr_build_kernel(const int* __restrict__ esrc,
                                 const int* __restrict__ edst)
{
    int t = blockIdx.x * blockDim.x + threadIdx.x;
    if (t >= NEDGT) return;
    int src[EPT], dst[EPT];
    #pragma unroll
    for (int q = 0; q < 2; q++) {
        int4 s = __ldg((const int4*)esrc + t * 2 + q);
        int4 d = __ldg((const int4*)edst + t * 2 + q);
        src[4*q+0] = s.x; src[4*q+1] = s.y; src[4*q+2] = s.z; src[4*q+3] = s.w;
        dst[4*q+0] = d.x; dst[4*q+1] = d.y; dst[4*q+2] = d.z; dst[4*q+3] = d.w;
    }
    #pragma unroll
    for (int q = 0; q < EPT; q++) {
        int pos = atomicAdd(&g_cnt[dst[q]], 1);
        if (pos < CAP) g_csrc[dst[q] * CAP + pos] = src[q];
    }
}

// ---- Tensor-core GEMM (128-row tile) + fused alpha + fp16 h emit ---------
__device__ __forceinline__ void gemm_mma_epilogue(
    char* smem, const float* __restrict__ a_src, const float* __restrict__ a_dst,
    __half* __restrict__ h16, float4* __restrict__ AS, float4* __restrict__ AD,
    int m0, int M, int tid)
{
    __half* Ah = (__half*)smem;
    __half* Wh = (__half*)(smem + AH_BYTES);
    float*  Cs = (float*)smem;

    int wid = tid >> 5;
    int wr  = wid >> 1;
    int wc  = wid & 1;

    wmma::fragment<wmma::accumulator, 16, 16, 16, float> cf[2][4];
    #pragma unroll
    for (int r = 0; r < 2; r++)
        #pragma unroll
        for (int n = 0; n < 4; n++) wmma::fill_fragment(cf[r][n], 0.f);

    #pragma unroll
    for (int kk = 0; kk < 8; kk++) {
        wmma::fragment<wmma::matrix_b, 16, 16, 16, __half, wmma::row_major> bf[4];
        #pragma unroll
        for (int n = 0; n < 4; n++)
            wmma::load_matrix_sync(bf[n], Wh + (kk * 16) * 136 + wc * 64 + n * 16, 136);
        #pragma unroll
        for (int r = 0; r < 2; r++) {
            wmma::fragment<wmma::matrix_a, 16, 16, 16, __half, wmma::row_major> af;
            wmma::load_matrix_sync(af, Ah + (wr * 32 + r * 16) * 136 + kk * 16, 136);
            #pragma unroll
            for (int n = 0; n < 4; n++)
                wmma::mma_sync(cf[r][n], af, bf[n], cf[r][n]);
        }
    }
    __syncthreads();

    #pragma unroll
    for (int r = 0; r < 2; r++)
        #pragma unroll
        for (int n = 0; n < 4; n++)
            wmma::store_matrix_sync(Cs + (wr * 32 + r * 16) * CS_PITCH + wc * 64 + n * 16,
                                    cf[r][n], CS_PITCH, wmma::mem_row_major);
    __syncthreads();

    int colg = tid & 15;
    int rowg = tid >> 4;

    float4 asl = __ldg((const float4*)a_src + colg);
    float4 ash = __ldg((const float4*)a_src + 16 + colg);
    float4 adl = __ldg((const float4*)a_dst + colg);
    float4 adh = __ldg((const float4*)a_dst + 16 + colg);

    #pragma unroll
    for (int i = 0; i < 8; i++) {
        int row = rowg * 8 + i;
        int gm = m0 + row;
        if (gm >= M) continue;
        float4 c0 = *(const float4*)(Cs + row * CS_PITCH + colg * 4);
        float4 c1 = *(const float4*)(Cs + row * CS_PITCH + 64 + colg * 4);

        __half2 ph0 = __float22half2_rn(make_float2(c0.x, c0.y));
        __half2 ph1 = __float22half2_rn(make_float2(c0.z, c0.w));
        __half2 ph2 = __float22half2_rn(make_float2(c1.x, c1.y));
        __half2 ph3 = __float22half2_rn(make_float2(c1.z, c1.w));
        *(uint2*)(h16 + gm * FDIM + colg * 4) =
            make_uint2(*(unsigned*)&ph0, *(unsigned*)&ph1);
        *(uint2*)(h16 + gm * FDIM + 64 + colg * 4) =
            make_uint2(*(unsigned*)&ph2, *(unsigned*)&ph3);

        float pls = c0.x * asl.x + c0.y * asl.y + c0.z * asl.z + c0.w * asl.w;
        float pld = c0.x * adl.x + c0.y * adl.y + c0.z * adl.z + c0.w * adl.w;
        float phs = c1.x * ash.x + c1.y * ash.y + c1.z * ash.z + c1.w * ash.w;
        float phd = c1.x * adh.x + c1.y * adh.y + c1.z * adh.z + c1.w * adh.w;
        #pragma unroll
        for (int o = 1; o < 8; o <<= 1) {
            pls += __shfl_xor_sync(0xffffffffu, pls, o);
            pld += __shfl_xor_sync(0xffffffffu, pld, o);
            phs += __shfl_xor_sync(0xffffffffu, phs, o);
            phd += __shfl_xor_sync(0xffffffffu, phd, o);
        }
        if ((colg & 7) == 0) {
            int g = colg >> 3;
            float* asp = (float*)(AS + gm);
            float* adp = (float*)(AD + gm);
            asp[g] = pls;  asp[2 + g] = phs;
            adp[g] = pld;  adp[2 + g] = phd;
        }
    }
}

// layer-1: A is fp32
__global__ __launch_bounds__(256) void gemm_tc_f32(
    const float* __restrict__ A, const float* __restrict__ Wm,
    const float* __restrict__ a_src, const float* __restrict__ a_dst,
    __half* __restrict__ h16, float4* __restrict__ AS, float4* __restrict__ AD,
    int M)
{
    extern __shared__ char smem[];
    __half* Ah = (__half*)smem;
    __half* Wh = (__half*)(smem + AH_BYTES);
    int tid = threadIdx.x;
    int m0  = blockIdx.x * BM;

    #pragma unroll
    for (int t = tid; t < 4096; t += 256) {
        int row = t >> 5, c4 = t & 31;
        float4 v = __ldg((const float4*)Wm + t);
        __half2 h0 = __float22half2_rn(make_float2(v.x, v.y));
        __half2 h1 = __float22half2_rn(make_float2(v.z, v.w));
        *(uint2*)(Wh + row * 136 + c4 * 4) = make_uint2(*(unsigned*)&h0, *(unsigned*)&h1);
    }
    #pragma unroll
    for (int t = tid; t < 4096; t += 256) {
        int row = t >> 5, c4 = t & 31;
        int gm = m0 + row;
        float4 v = (gm < M) ? __ldg((const float4*)A + gm * 32 + c4)
                            : make_float4(0.f, 0.f, 0.f, 0.f);
        __half2 h0 = __float22half2_rn(make_float2(v.x, v.y));
        __half2 h1 = __float22half2_rn(make_float2(v.z, v.w));
        *(uint2*)(Ah + row * 136 + c4 * 4) = make_uint2(*(unsigned*)&h0, *(unsigned*)&h1);
    }
    __syncthreads();
    gemm_mma_epilogue(smem, a_src, a_dst, h16, AS, AD, m0, M, tid);
}

// layer-2: A is fp16; m0base offsets the row range (chunked pipeline)
__global__ __launch_bounds__(256) void gemm_tc_f16(
    const __half* __restrict__ A, const float* __restrict__ Wm,
    const float* __restrict__ a_src, const float* __restrict__ a_dst,
    __half* __restrict__ h16, float4* __restrict__ AS, float4* __restrict__ AD,
    int m0base, int M)
{
    extern __shared__ char smem[];
    __half* Ah = (__half*)smem;
    __half* Wh = (__half*)(smem + AH_BYTES);
    int tid = threadIdx.x;
    int m0  = m0base + blockIdx.x * BM;

    #pragma unroll
    for (int t = tid; t < 4096; t += 256) {
        int row = t >> 5, c4 = t & 31;
        float4 v = __ldg((const float4*)Wm + t);
        __half2 h0 = __float22half2_rn(make_float2(v.x, v.y));
        __half2 h1 = __float22half2_rn(make_float2(v.z, v.w));
        *(uint2*)(Wh + row * 136 + c4 * 4) = make_uint2(*(unsigned*)&h0, *(unsigned*)&h1);
    }
    #pragma unroll
    for (int t = tid; t < 2048; t += 256) {
        int row = t >> 4, c8 = t & 15;
        int gm = m0 + row;
        uint4 v = make_uint4(0u, 0u, 0u, 0u);
        if (gm < M) v = __ldg((const uint4*)(A + gm * FDIM) + c8);
        *(uint4*)(Ah + row * 136 + c8 * 8) = v;
    }
    __syncthreads();
    gemm_mma_epilogue(smem, a_src, a_dst, h16, AS, AD, m0, M, tid);
}

// ------- aggregation: 2 edges/warp-inst, 8 dims/lane (R12 ops, 8-deep) ----
__device__ __forceinline__ float leaky(float e) { return fmaxf(e, 0.2f * e); }

__device__ __forceinline__ void agg_edge(
    const __half* __restrict__ h, const float* __restrict__ ASf,
    int s, float adh, int head, int li,
    ull& a0, ull& a1, ull& a2, ull& a3, float& wsum)
{
    float a = __ldg(ASf + s * 4 + head);
    uint4 hx = __ldg((const uint4*)(h + s * FDIM) + li);
    float w = __expf(leaky(a + adh));
    wsum += w;
    ull wp = pk2(w);
    ffma2(a0, wp, h2pair(hx.x));
    ffma2(a1, wp, h2pair(hx.y));
    ffma2(a2, wp, h2pair(hx.z));
    ffma2(a3, wp, h2pair(hx.w));
}

// half = lane>>4 picks edge parity, li = lane&15 carries dims 8li..8li+7
__device__ __forceinline__ void agg_body2(
    const __half* __restrict__ h, const float4* __restrict__ AS,
    const float4* __restrict__ AD,
    int gw, int half, int li, int head, int cnt,
    float2 (&ov)[4], float& wsum)
{
    const int* row = g_csrc + gw * CAP;
    const float* ASf = (const float*)AS;
    float adh = __ldg(((const float*)(AD + gw)) + head);

    // self loop: half 0 only (half 1 adds exact 0)
    float wself = (half == 0) ? __expf(leaky(__ldg(ASf + gw * 4 + head) + adh)) : 0.f;
    wsum = wself;
    uint4 hv = __ldg((const uint4*)(h + gw * FDIM) + li);
    ull acc0 = 0ull, acc1 = 0ull, acc2 = 0ull, acc3 = 0ull;
    {
        ull wp = pk2(wself);
        ffma2(acc0, wp, h2pair(hv.x));
        ffma2(acc1, wp, h2pair(hv.y));
        ffma2(acc2, wp, h2pair(hv.z));
        ffma2(acc3, wp, h2pair(hv.w));
    }

    int j = 0;
    // 8 edges per iteration (4 per half, in flight together for MLP)
    for (; j + 8 <= cnt; j += 8) {
        int s0 = __ldg(row + j + half);
        int s1 = __ldg(row + j + 2 + half);
        int s2 = __ldg(row + j + 4 + half);
        int s3 = __ldg(row + j + 6 + half);
        agg_edge(h, ASf, s0, adh, head, li, acc0, acc1, acc2, acc3, wsum);
        agg_edge(h, ASf, s1, adh, head, li, acc0, acc1, acc2, acc3, wsum);
        agg_edge(h, ASf, s2, adh, head, li, acc0, acc1, acc2, acc3, wsum);
        agg_edge(h, ASf, s3, adh, head, li, acc0, acc1, acc2, acc3, wsum);
    }
    for (; j + 2 <= cnt; j += 2) {
        int s = __ldg(row + j + half);
        agg_edge(h, ASf, s, adh, head, li, acc0, acc1, acc2, acc3, wsum);
    }
    if (j < cnt) {   // odd tail: half 0 processes, half 1 adds exact 0
        int s = (half == 0) ? __ldg(row + j) : gw;
        float w = (half == 0) ? __expf(leaky(__ldg(ASf + s * 4 + head) + adh)) : 0.f;
        uint4 hx = __ldg((const uint4*)(h + s * FDIM) + li);
        wsum += w;
        ull wp = pk2(w);
        ffma2(acc0, wp, h2pair(hx.x));
        ffma2(acc1, wp, h2pair(hx.y));
        ffma2(acc2, wp, h2pair(hx.z));
        ffma2(acc3, wp, h2pair(hx.w));
    }

    ov[0] = up2(acc0); ov[1] = up2(acc1); ov[2] = up2(acc2); ov[3] = up2(acc3);
    #pragma unroll
    for (int k = 0; k < 4; k++) {
        ov[k].x += __shfl_xor_sync(0xffffffffu, ov[k].x, 16);
        ov[k].y += __shfl_xor_sync(0xffffffffu, ov[k].y, 16);
    }
    wsum += __shfl_xor_sync(0xffffffffu, wsum, 16);
}

// layer-1 (chunked): feat out in fp16 for nodes [base, base+nn)
__global__ __launch_bounds__(256) void agg_fused_kernel(
    const __half* __restrict__ h, const float* __restrict__ bias,
    __half* __restrict__ feat16, int base, int nn)
{
    int gl = (blockIdx.x * blockDim.x + threadIdx.x) >> 5;
    if (gl >= nn) return;
    int gw = base + gl;
    int lane = threadIdx.x & 31;
    int half = lane >> 4, li = lane & 15, head = li >> 2;
    int cnt  = min(__ldg(&g_cnt[gw]), CAP);

    float2 ov[4];
    float wsum;
    agg_body2(h, g_AS1, g_AD1, gw, half, li, head, cnt, ov, wsum);

    if (half == 0) {
        float inv = __fdividef(1.f, wsum + 1e-16f);
        float4 b0 = __ldg((const float4*)bias + li * 2);
        float4 b1 = __ldg((const float4*)bias + li * 2 + 1);
        float o0 = fmaxf(fmaf(ov[0].x, inv, b0.x), 0.f);
        float o1 = fmaxf(fmaf(ov[0].y, inv, b0.y), 0.f);
        float o2 = fmaxf(fmaf(ov[1].x, inv, b0.z), 0.f);
        float o3 = fmaxf(fmaf(ov[1].y, inv, b0.w), 0.f);
        float o4 = fmaxf(fmaf(ov[2].x, inv, b1.x), 0.f);
        float o5 = fmaxf(fmaf(ov[2].y, inv, b1.y), 0.f);
        float o6 = fmaxf(fmaf(ov[3].x, inv, b1.z), 0.f);
        float o7 = fmaxf(fmaf(ov[3].y, inv, b1.w), 0.f);
        __half2 q0 = __float22half2_rn(make_float2(o0, o1));
        __half2 q1 = __float22half2_rn(make_float2(o2, o3));
        __half2 q2 = __float22half2_rn(make_float2(o4, o5));
        __half2 q3 = __float22half2_rn(make_float2(o6, o7));
        *(uint4*)(feat16 + gw * FDIM + li * 8) =
            make_uint4(*(unsigned*)&q0, *(unsigned*)&q1,
                       *(unsigned*)&q2, *(unsigned*)&q3);
    }
}

// layer-2: fused classifier dot + sigmoid + cnt reset (full range)
__global__ __launch_bounds__(256) void agg_final_kernel(
    const __half* __restrict__ h, const float* __restrict__ bias,
    float* __restrict__ out)
{
    int gw = (blockIdx.x * blockDim.x + threadIdx.x) >> 5;
    if (gw >= NN) return;
    int lane = threadIdx.x & 31;
    int half = lane >> 4, li = lane & 15, head = li >> 2;
    int cnt  = min(__ldg(&g_cnt[gw]), CAP);

    float2 ov[4];
    float wsum;
    agg_body2(h, g_AS2, g_AD2, gw, half, li, head, cnt, ov, wsum);

    float inv = __fdividef(1.f, wsum + 1e-16f);
    float4 b0 = __ldg((const float4*)bias + li * 2);
    float4 b1 = __ldg((const float4*)bias + li * 2 + 1);
    float o0 = fmaxf(fmaf(ov[0].x, inv, b0.x), 0.f);
    float o1 = fmaxf(fmaf(ov[0].y, inv, b0.y), 0.f);
    float o2 = fmaxf(fmaf(ov[1].x, inv, b0.z), 0.f);
    float o3 = fmaxf(fmaf(ov[1].y, inv, b0.w), 0.f);
    float o4 = fmaxf(fmaf(ov[2].x, inv, b1.x), 0.f);
    float o5 = fmaxf(fmaf(ov[2].y, inv, b1.y), 0.f);
    float o6 = fmaxf(fmaf(ov[3].x, inv, b1.z), 0.f);
    float o7 = fmaxf(fmaf(ov[3].y, inv, b1.w), 0.f);

    float4 w0 = __ldg((const float4*)g_weff + li * 2);
    float4 w1 = __ldg((const float4*)g_weff + li * 2 + 1);
    float p = o0 * w0.x + o1 * w0.y + o2 * w0.z + o3 * w0.w
            + o4 * w1.x + o5 * w1.y + o6 * w1.z + o7 * w1.w;
    #pragma unroll
    for (int of = 8; of >= 1; of >>= 1)
        p += __shfl_xor_sync(0xffffffffu, p, of);
    if (lane == 0) {
        float z = p + g_beff;
        out[gw] = __fdividef(1.f, 1.f + __expf(-z));
        g_cnt[gw] = 0;                     // reset for the next invocation
    }
}

// ---------------- classifier folding: w_eff = Wc1 @ Wc2 ------------------
__global__ void weff_kernel(const float* __restrict__ Wc1,
                            const float* __restrict__ bc1,
                            const float* __restrict__ Wc2,
                            const float* __restrict__ bc2)
{
    int t = threadIdx.x;
    if (t < 128) {
        float s = 0.f;
        #pragma unroll
        for (int j = 0; j < 32; j++) s += Wc1[t * 32 + j] * Wc2[j];
        g_weff[t] = s;
    }
    if (t == 0) {
        float b = bc2[0];
        for (int j = 0; j < 32; j++) b += bc1[j] * Wc2[j];
        g_beff = b;
    }
}

// ---------------- host launcher ----------------
extern "C" void kernel_launch(void* const* d_in, const int* in_sizes, int n_in,
                              void* d_out, int out_size)
{
    const float* x    = (const float*)d_in[0];
    const int*   ei   = (const int*)  d_in[1];
    const int*   esrc = ei;
    const int*   edst = ei + NE;
    const float* W1   = (const float*)d_in[2];
    const float* as1  = (const float*)d_in[3];
    const float* ad1  = (const float*)d_in[4];
    const float* b1   = (const float*)d_in[5];
    const float* W2   = (const float*)d_in[6];
    const float* as2  = (const float*)d_in[7];
    const float* ad2  = (const float*)d_in[8];
    const float* b2   = (const float*)d_in[9];
    const float* Wc1  = (const float*)d_in[10];
    const float* bc1  = (const float*)d_in[11];
    const float* Wc2  = (const float*)d_in[12];
    const float* bc2  = (const float*)d_in[13];
    float* out = (float*)d_out;

    __half *h16a, *h16b, *feat16;
    float4 *AS1, *AD1, *AS2, *AD2;
    cudaGetSymbolAddress((void**)&h16a,   g_h16a);
    cudaGetSymbolAddress((void**)&h16b,   g_h16b);
    cudaGetSymbolAddress((void**)&feat16, g_feat16);
    cudaGetSymbolAddress((void**)&AS1,    g_AS1);
    cudaGetSymbolAddress((void**)&AD1,    g_AD1);
    cudaGetSymbolAddress((void**)&AS2,    g_AS2);
    cudaGetSymbolAddress((void**)&AD2,    g_AD2);

    static cudaStream_t s2 = nullptr;
    static cudaEvent_t evFork = nullptr, evJoin = nullptr, evG = nullptr;
    static cudaEvent_t evA[NCHUNK] = {nullptr, nullptr, nullptr, nullptr};
    if (!s2) {
        cudaStreamCreateWithFlags(&s2, cudaStreamNonBlocking);
        cudaEventCreateWithFlags(&evFork, cudaEventDisableTiming);
        cudaEventCreateWithFlags(&evJoin, cudaEventDisableTiming);
        cudaEventCreateWithFlags(&evG, cudaEventDisableTiming);
        for (int k = 0; k < NCHUNK; k++)
            cudaEventCreateWithFlags(&evA[k], cudaEventDisableTiming);
    }

    cudaFuncSetAttribute(gemm_tc_f32,
                         cudaFuncAttributeMaxDynamicSharedMemorySize, GEMM_SMEM);
    cudaFuncSetAttribute(gemm_tc_f16,
                         cudaFuncAttributeMaxDynamicSharedMemorySize, GEMM_SMEM);

    const int warpGrid = (NN * 32 + 255) / 256;
    const int gemmGrid = (NN + BM - 1) / BM;
    const int eGrid    = (NEDGT + 255) / 256;

    // Fork: one-pass padded-CSR build + weff concurrent with GEMM1
    cudaEventRecord(evFork, 0);
    cudaStreamWaitEvent(s2, evFork, 0);
    csr_build_kernel<<<eGrid, 256, 0, s2>>>(esrc, edst);
    weff_kernel<<<1, 128, 0, s2>>>(Wc1, bc1, Wc2, bc2);
    cudaEventRecord(evJoin, s2);            // CSR + weff ready

    // Layer 1: TC GEMM + alphas fused
    gemm_tc_f32<<<gemmGrid, 256, GEMM_SMEM>>>(x, W1, as1, ad1, h16a, AS1, AD1, NN);

    cudaStreamWaitEvent(0, evJoin, 0);

    // agg1 chunks on stream 0; GEMM2 chunks pipelined on s2
    for (int k = 0; k < NCHUNK; k++) {
        int base = k * CHUNK;
        int nn   = (k == NCHUNK - 1) ? (NN - base) : CHUNK;
        int grid = (nn * 32 + 255) / 256;
        agg_fused_kernel<<<grid, 256>>>(h16a, b1, feat16, base, nn);
        cudaEventRecord(evA[k], 0);
        cudaStreamWaitEvent(s2, evA[k], 0);
        int tiles = (nn + BM - 1) / BM;
        gemm_tc_f16<<<tiles, 256, GEMM_SMEM, s2>>>(feat16, W2, as2, ad2,
                                                   h16b, AS2, AD2, base, NN);
    }
    cudaEventRecord(evG, s2);

    // Layer-2 aggregation + classifier (needs all GEMM2 chunks)
    cudaStreamWaitEvent(0, evG, 0);
    agg_final_kernel<<<warpGrid, 256>>>(h16b, b2, out);
}

// round 16
// speedup vs baseline: 1.1533x; 1.1533x over previous
#include <cuda_runtime.h>
#include <cuda_fp16.h>
#include <mma.h>

using namespace nvcuda;

// Problem constants (fixed by reference)
#define NN    50000
#define NE    800000
#define FDIM  128
#define CAP   64                          // padded CSR row capacity (Poisson(16))

#define EPT   4
#define NEDGT (NE / EPT)                  // 200000 edge-threads

typedef unsigned long long ull;

// smem layout for the TC GEMM (128-row tiles)
#define BM        128
#define AH_BYTES  (BM * 136 * 2)            // 34816
#define WH_BYTES  (128 * 136 * 2)           // 34816
#define GEMM_SMEM (AH_BYTES + WH_BYTES)     // 69632
#define CS_PITCH  132

// ---------------- scratch (device globals; no runtime allocation) ----------
__device__ __half g_h16[NN * FDIM];        // fp16 gather table
__device__ __half g_feat16[NN * FDIM];     // layer-1 output (fp16, GEMM2 input)
__device__ __half g_W2h[FDIM * FDIM];      // pre-converted W2 (fp16)
__device__ float4 g_AS[NN];
__device__ float4 g_AD[NN];
__device__ int    g_cnt[NN];               // zero at entry; agg_final re-zeros
__device__ int    g_csrc[NN * CAP];        // padded CSR (12.8 MB)
__device__ float  g_weff[FDIM];
__device__ float  g_beff;

// ---------------- packed f32x2 helpers ----------------
__device__ __forceinline__ ull pk2(float v) {
    ull r; asm("mov.b64 %0, {%1, %1};" : "=l"(r) : "f"(v)); return r;
}
__device__ __forceinline__ void ffma2(ull& d, ull a, ull b) {
    asm("fma.rn.f32x2 %0, %1, %2, %0;" : "+l"(d) : "l"(a), "l"(b));
}
__device__ __forceinline__ float2 up2(ull r) {
    float2 f; asm("mov.b64 {%0, %1}, %2;" : "=f"(f.x), "=f"(f.y) : "l"(r)); return f;
}
__device__ __forceinline__ ull h2pair(unsigned u) {
    __half2 hh = *(__half2*)&u;
    float2 f = __half22float2(hh);
    ull p; asm("mov.b64 %0, {%1, %2};" : "=l"(p) : "f"(f.x), "f"(f.y));
    return p;
}

// ---------------- padded-CSR build: ONE pass, EPT=4 for 2x parallelism ----
__global__ void csr_build_kernel(const int* __restrict__ esrc,
                                 const int* __restrict__ edst)
{
    int t = blockIdx.x * blockDim.x + threadIdx.x;
    if (t >= NEDGT) return;
    int4 s = __ldg((const int4*)esrc + t);
    int4 d = __ldg((const int4*)edst + t);
    int p0 = atomicAdd(&g_cnt[d.x], 1);
    int p1 = atomicAdd(&g_cnt[d.y], 1);
    int p2 = atomicAdd(&g_cnt[d.z], 1);
    int p3 = atomicAdd(&g_cnt[d.w], 1);
    if (p0 < CAP) g_csrc[d.x * CAP + p0] = s.x;
    if (p1 < CAP) g_csrc[d.y * CAP + p1] = s.y;
    if (p2 < CAP) g_csrc[d.z * CAP + p2] = s.z;
    if (p3 < CAP) g_csrc[d.w * CAP + p3] = s.w;
}

// ---------------- W2 fp32 -> fp16 pre-conversion (side stream) ------------
__global__ void wconv_kernel(const float* __restrict__ W, __half* __restrict__ Wh) {
    int t = blockIdx.x * blockDim.x + threadIdx.x;   // 4096 float4s
    if (t >= 4096) return;
    float4 v = __ldg((const float4*)W + t);
    __half2 h0 = __float22half2_rn(make_float2(v.x, v.y));
    __half2 h1 = __float22half2_rn(make_float2(v.z, v.w));
    *(uint2*)(Wh + t * 4) = make_uint2(*(unsigned*)&h0, *(unsigned*)&h1);
}

// ---- Tensor-core GEMM (128-row tile) + fused alpha + fp16 h emit ---------
__device__ __forceinline__ void gemm_mma_epilogue(
    char* smem, const float* __restrict__ a_src, const float* __restrict__ a_dst,
    __half* __restrict__ h16, int m0, int M, int tid)
{
    __half* Ah = (__half*)smem;
    __half* Wh = (__half*)(smem + AH_BYTES);
    float*  Cs = (float*)smem;

    int wid = tid >> 5;
    int wr  = wid >> 1;
    int wc  = wid & 1;

    wmma::fragment<wmma::accumulator, 16, 16, 16, float> cf[2][4];
    #pragma unroll
    for (int r = 0; r < 2; r++)
        #pragma unroll
        for (int n = 0; n < 4; n++) wmma::fill_fragment(cf[r][n], 0.f);

    #pragma unroll
    for (int kk = 0; kk < 8; kk++) {
        wmma::fragment<wmma::matrix_b, 16, 16, 16, __half, wmma::row_major> bf[4];
        #pragma unroll
        for (int n = 0; n < 4; n++)
            wmma::load_matrix_sync(bf[n], Wh + (kk * 16) * 136 + wc * 64 + n * 16, 136);
        #pragma unroll
        for (int r = 0; r < 2; r++) {
            wmma::fragment<wmma::matrix_a, 16, 16, 16, __half, wmma::row_major> af;
            wmma::load_matrix_sync(af, Ah + (wr * 32 + r * 16) * 136 + kk * 16, 136);
            #pragma unroll
            for (int n = 0; n < 4; n++)
                wmma::mma_sync(cf[r][n], af, bf[n], cf[r][n]);
        }
    }
    __syncthreads();

    #pragma unroll
    for (int r = 0; r < 2; r++)
        #pragma unroll
        for (int n = 0; n < 4; n++)
            wmma::store_matrix_sync(Cs + (wr * 32 + r * 16) * CS_PITCH + wc * 64 + n * 16,
                                    cf[r][n], CS_PITCH, wmma::mem_row_major);
    __syncthreads();

    int colg = tid & 15;
    int rowg = tid >> 4;

    float4 asl = __ldg((const float4*)a_src + colg);
    float4 ash = __ldg((const float4*)a_src + 16 + colg);
    float4 adl = __ldg((const float4*)a_dst + colg);
    float4 adh = __ldg((const float4*)a_dst + 16 + colg);

    #pragma unroll
    for (int i = 0; i < 8; i++) {
        int row = rowg * 8 + i;
        int gm = m0 + row;
        if (gm >= M) continue;
        float4 c0 = *(const float4*)(Cs + row * CS_PITCH + colg * 4);
        float4 c1 = *(const float4*)(Cs + row * CS_PITCH + 64 + colg * 4);

        __half2 ph0 = __float22half2_rn(make_float2(c0.x, c0.y));
        __half2 ph1 = __float22half2_rn(make_float2(c0.z, c0.w));
        __half2 ph2 = __float22half2_rn(make_float2(c1.x, c1.y));
        __half2 ph3 = __float22half2_rn(make_float2(c1.z, c1.w));
        *(uint2*)(h16 + gm * FDIM + colg * 4) =
            make_uint2(*(unsigned*)&ph0, *(unsigned*)&ph1);
        *(uint2*)(h16 + gm * FDIM + 64 + colg * 4) =
            make_uint2(*(unsigned*)&ph2, *(unsigned*)&ph3);

        float pls = c0.x * asl.x + c0.y * asl.y + c0.z * asl.z + c0.w * asl.w;
        float pld = c0.x * adl.x + c0.y * adl.y + c0.z * adl.z + c0.w * adl.w;
        float phs = c1.x * ash.x + c1.y * ash.y + c1.z * ash.z + c1.w * ash.w;
        float phd = c1.x * adh.x + c1.y * adh.y + c1.z * adh.z + c1.w * adh.w;
        #pragma unroll
        for (int o = 1; o < 8; o <<= 1) {
            pls += __shfl_xor_sync(0xffffffffu, pls, o);
            pld += __shfl_xor_sync(0xffffffffu, pld, o);
            phs += __shfl_xor_sync(0xffffffffu, phs, o);
            phd += __shfl_xor_sync(0xffffffffu, phd, o);
        }
        if ((colg & 7) == 0) {
            int g = colg >> 3;
            float* asp = (float*)(g_AS + gm);
            float* adp = (float*)(g_AD + gm);
            asp[g] = pls;  asp[2 + g] = phs;
            adp[g] = pld;  adp[2 + g] = phd;
        }
    }
}

// layer-1: A is fp32, W converted in-kernel (must start immediately)
__global__ __launch_bounds__(256) void gemm_tc_f32(
    const float* __restrict__ A, const float* __restrict__ Wm,
    const float* __restrict__ a_src, const float* __restrict__ a_dst,
    __half* __restrict__ h16, int M)
{
    extern __shared__ char smem[];
    __half* Ah = (__half*)smem;
    __half* Wh = (__half*)(smem + AH_BYTES);
    int tid = threadIdx.x;
    int m0  = blockIdx.x * BM;

    #pragma unroll
    for (int t = tid; t < 4096; t += 256) {
        int row = t >> 5, c4 = t & 31;
        float4 v = __ldg((const float4*)Wm + t);
        __half2 h0 = __float22half2_rn(make_float2(v.x, v.y));
        __half2 h1 = __float22half2_rn(make_float2(v.z, v.w));
        *(uint2*)(Wh + row * 136 + c4 * 4) = make_uint2(*(unsigned*)&h0, *(unsigned*)&h1);
    }
    #pragma unroll
    for (int t = tid; t < 4096; t += 256) {
        int row = t >> 5, c4 = t & 31;
        int gm = m0 + row;
        float4 v = (gm < M) ? __ldg((const float4*)A + gm * 32 + c4)
                            : make_float4(0.f, 0.f, 0.f, 0.f);
        __half2 h0 = __float22half2_rn(make_float2(v.x, v.y));
        __half2 h1 = __float22half2_rn(make_float2(v.z, v.w));
        *(uint2*)(Ah + row * 136 + c4 * 4) = make_uint2(*(unsigned*)&h0, *(unsigned*)&h1);
    }
    __syncthreads();
    gemm_mma_epilogue(smem, a_src, a_dst, h16, m0, M, tid);
}

// layer-2: A is fp16, W pre-converted fp16 (half the staging bytes, no cvt)
__global__ __launch_bounds__(256) void gemm_tc_f16(
    const __half* __restrict__ A, const __half* __restrict__ Wh16,
    const float* __restrict__ a_src, const float* __restrict__ a_dst,
    __half* __restrict__ h16, int M)
{
    extern __shared__ char smem[];
    __half* Ah = (__half*)smem;
    __half* Wh = (__half*)(smem + AH_BYTES);
    int tid = threadIdx.x;
    int m0  = blockIdx.x * BM;

    #pragma unroll
    for (int t = tid; t < 2048; t += 256) {          // 128 rows x 16 uint4
        int row = t >> 4, c8 = t & 15;
        uint4 v = __ldg((const uint4*)Wh16 + t);
        *(uint4*)(Wh + row * 136 + c8 * 8) = v;
    }
    #pragma unroll
    for (int t = tid; t < 2048; t += 256) {
        int row = t >> 4, c8 = t & 15;
        int gm = m0 + row;
        uint4 v = make_uint4(0u, 0u, 0u, 0u);
        if (gm < M) v = __ldg((const uint4*)(A + gm * FDIM) + c8);
        *(uint4*)(Ah + row * 136 + c8 * 8) = v;
    }
    __syncthreads();
    gemm_mma_epilogue(smem, a_src, a_dst, h16, m0, M, tid);
}

// ------- aggregation: 2 edges/warp-inst, 8 dims/lane (R12 structure) ------
__device__ __forceinline__ float leaky(float e) { return fmaxf(e, 0.2f * e); }

// half = lane>>4 picks edge parity, li = lane&15 carries dims 8li..8li+7
// head = li>>2.
__device__ __forceinline__ void agg_body2(
    const __half* __restrict__ h, int gw, int half, int li, int head, int cnt,
    float2 (&ov)[4], float& wsum)
{
    const int* row = g_csrc + gw * CAP;
    const float* ASf = (const float*)g_AS;
    float adh = __ldg(((const float*)(g_AD + gw)) + head);

    // self loop: half 0 only (half 1 adds exact 0)
    float wself = (half == 0) ? __expf(leaky(__ldg(ASf + gw * 4 + head) + adh)) : 0.f;
    wsum = wself;
    uint4 hv = __ldg((const uint4*)(h + gw * FDIM) + li);
    ull acc0 = 0ull, acc1 = 0ull, acc2 = 0ull, acc3 = 0ull;
    {
        ull wp = pk2(wself);
        ffma2(acc0, wp, h2pair(hv.x));
        ffma2(acc1, wp, h2pair(hv.y));
        ffma2(acc2, wp, h2pair(hv.z));
        ffma2(acc3, wp, h2pair(hv.w));
    }

    int j = 0;
    // 4 edges per iteration (2 per warp-inst, unroll x2 for MLP)
    for (; j + 4 <= cnt; j += 4) {
        int sA = __ldg(row + j + half);
        int sB = __ldg(row + j + 2 + half);
        float aA = __ldg(ASf + sA * 4 + head);
        float aB = __ldg(ASf + sB * 4 + head);
        uint4 hA = __ldg((const uint4*)(h + sA * FDIM) + li);
        uint4 hB = __ldg((const uint4*)(h + sB * FDIM) + li);
        float wA = __expf(leaky(aA + adh));
        float wB = __expf(leaky(aB + adh));
        wsum += wA + wB;
        ull wpA = pk2(wA), wpB = pk2(wB);
        ffma2(acc0, wpA, h2pair(hA.x));  ffma2(acc0, wpB, h2pair(hB.x));
        ffma2(acc1, wpA, h2pair(hA.y));  ffma2(acc1, wpB, h2pair(hB.y));
        ffma2(acc2, wpA, h2pair(hA.z));  ffma2(acc2, wpB, h2pair(hB.z));
        ffma2(acc3, wpA, h2pair(hA.w));  ffma2(acc3, wpB, h2pair(hB.w));
    }
    for (; j + 2 <= cnt; j += 2) {
        int s = __ldg(row + j + half);
        float a = __ldg(ASf + s * 4 + head);
        uint4 hx = __ldg((const uint4*)(h + s * FDIM) + li);
        float w = __expf(leaky(a + adh));
        wsum += w;
        ull wp = pk2(w);
        ffma2(acc0, wp, h2pair(hx.x));
        ffma2(acc1, wp, h2pair(hx.y));
        ffma2(acc2, wp, h2pair(hx.z));
        ffma2(acc3, wp, h2pair(hx.w));
    }
    if (j < cnt) {   // odd tail: half 0 processes, half 1 adds exact 0
        int s = (half == 0) ? __ldg(row + j) : gw;
        float w = (half == 0) ? __expf(leaky(__ldg(ASf + s * 4 + head) + adh)) : 0.f;
        uint4 hx = __ldg((const uint4*)(h + s * FDIM) + li);
        wsum += w;
        ull wp = pk2(w);
        ffma2(acc0, wp, h2pair(hx.x));
        ffma2(acc1, wp, h2pair(hx.y));
        ffma2(acc2, wp, h2pair(hx.z));
        ffma2(acc3, wp, h2pair(hx.w));
    }

    // combine the two halves (lane i <-> lane i^16)
    ov[0] = up2(acc0); ov[1] = up2(acc1); ov[2] = up2(acc2); ov[3] = up2(acc3);
    #pragma unroll
    for (int k = 0; k < 4; k++) {
        ov[k].x += __shfl_xor_sync(0xffffffffu, ov[k].x, 16);
        ov[k].y += __shfl_xor_sync(0xffffffffu, ov[k].y, 16);
    }
    wsum += __shfl_xor_sync(0xffffffffu, wsum, 16);
}

// layer-1: feat out in fp16
__global__ __launch_bounds__(256) void agg_fused_kernel(
    const __half* __restrict__ h, const float* __restrict__ bias,
    __half* __restrict__ feat16)
{
    int gw = (blockIdx.x * blockDim.x + threadIdx.x) >> 5;
    if (gw >= NN) return;
    int lane = threadIdx.x & 31;
    int half = lane >> 4, li = lane & 15, head = li >> 2;
    int cnt  = min(__ldg(&g_cnt[gw]), CAP);

    float2 ov[4];
    float wsum;
    agg_body2(h, gw, half, li, head, cnt, ov, wsum);

    if (half == 0) {
        float inv = __fdividef(1.f, wsum + 1e-16f);
        float4 b0 = __ldg((const float4*)bias + li * 2);
        float4 b1 = __ldg((const float4*)bias + li * 2 + 1);
        float o0 = fmaxf(fmaf(ov[0].x, inv, b0.x), 0.f);
        float o1 = fmaxf(fmaf(ov[0].y, inv, b0.y), 0.f);
        float o2 = fmaxf(fmaf(ov[1].x, inv, b0.z), 0.f);
        float o3 = fmaxf(fmaf(ov[1].y, inv, b0.w), 0.f);
        float o4 = fmaxf(fmaf(ov[2].x, inv, b1.x), 0.f);
        float o5 = fmaxf(fmaf(ov[2].y, inv, b1.y), 0.f);
        float o6 = fmaxf(fmaf(ov[3].x, inv, b1.z), 0.f);
        float o7 = fmaxf(fmaf(ov[3].y, inv, b1.w), 0.f);
        __half2 q0 = __float22half2_rn(make_float2(o0, o1));
        __half2 q1 = __float22half2_rn(make_float2(o2, o3));
        __half2 q2 = __float22half2_rn(make_float2(o4, o5));
        __half2 q3 = __float22half2_rn(make_float2(o6, o7));
        *(uint4*)(feat16 + gw * FDIM + li * 8) =
            make_uint4(*(unsigned*)&q0, *(unsigned*)&q1,
                       *(unsigned*)&q2, *(unsigned*)&q3);
    }
}

// layer-2: fused classifier dot + sigmoid + cnt reset
__global__ __launch_bounds__(256) void agg_final_kernel(
    const __half* __restrict__ h, const float* __restrict__ bias,
    float* __restrict__ out)
{
    int gw = (blockIdx.x * blockDim.x + threadIdx.x) >> 5;
    if (gw >= NN) return;
    int lane = threadIdx.x & 31;
    int half = lane >> 4, li = lane & 15, head = li >> 2;
    int cnt  = min(__ldg(&g_cnt[gw]), CAP);

    float2 ov[4];
    float wsum;
    agg_body2(h, gw, half, li, head, cnt, ov, wsum);

    float inv = __fdividef(1.f, wsum + 1e-16f);
    float4 b0 = __ldg((const float4*)bias + li * 2);
    float4 b1 = __ldg((const float4*)bias + li * 2 + 1);
    float o0 = fmaxf(fmaf(ov[0].x, inv, b0.x), 0.f);
    float o1 = fmaxf(fmaf(ov[0].y, inv, b0.y), 0.f);
    float o2 = fmaxf(fmaf(ov[1].x, inv, b0.z), 0.f);
    float o3 = fmaxf(fmaf(ov[1].y, inv, b0.w), 0.f);
    float o4 = fmaxf(fmaf(ov[2].x, inv, b1.x), 0.f);
    float o5 = fmaxf(fmaf(ov[2].y, inv, b1.y), 0.f);
    float o6 = fmaxf(fmaf(ov[3].x, inv, b1.z), 0.f);
    float o7 = fmaxf(fmaf(ov[3].y, inv, b1.w), 0.f);

    float4 w0 = __ldg((const float4*)g_weff + li * 2);
    float4 w1 = __ldg((const float4*)g_weff + li * 2 + 1);
    float p = o0 * w0.x + o1 * w0.y + o2 * w0.z + o3 * w0.w
            + o4 * w1.x + o5 * w1.y + o6 * w1.z + o7 * w1.w;
    #pragma unroll
    for (int of = 8; of >= 1; of >>= 1)
        p += __shfl_xor_sync(0xffffffffu, p, of);
    if (lane == 0) {
        float z = p + g_beff;
        out[gw] = __fdividef(1.f, 1.f + __expf(-z));
        g_cnt[gw] = 0;                     // reset for the next invocation
    }
}

// ---------------- classifier folding: w_eff = Wc1 @ Wc2 ------------------
__global__ void weff_kernel(const float* __restrict__ Wc1,
                            const float* __restrict__ bc1,
                            const float* __restrict__ Wc2,
                            const float* __restrict__ bc2)
{
    int t = threadIdx.x;
    if (t < 128) {
        float s = 0.f;
        #pragma unroll
        for (int j = 0; j < 32; j++) s += Wc1[t * 32 + j] * Wc2[j];
        g_weff[t] = s;
    }
    if (t == 0) {
        float b = bc2[0];
        for (int j = 0; j < 32; j++) b += bc1[j] * Wc2[j];
        g_beff = b;
    }
}

// ---------------- host launcher ----------------
extern "C" void kernel_launch(void* const* d_in, const int* in_sizes, int n_in,
                              void* d_out, int out_size)
{
    const float* x    = (const float*)d_in[0];
    const int*   ei   = (const int*)  d_in[1];
    const int*   esrc = ei;
    const int*   edst = ei + NE;
    const float* W1   = (const float*)d_in[2];
    const float* as1  = (const float*)d_in[3];
    const float* ad1  = (const float*)d_in[4];
    const float* b1   = (const float*)d_in[5];
    const float* W2   = (const float*)d_in[6];
    const float* as2  = (const float*)d_in[7];
    const float* ad2  = (const float*)d_in[8];
    const float* b2   = (const float*)d_in[9];
    const float* Wc1  = (const float*)d_in[10];
    const float* bc1  = (const float*)d_in[11];
    const float* Wc2  = (const float*)d_in[12];
    const float* bc2  = (const float*)d_in[13];
    float* out = (float*)d_out;

    __half *h16, *feat16, *W2h;
    cudaGetSymbolAddress((void**)&h16,    g_h16);
    cudaGetSymbolAddress((void**)&feat16, g_feat16);
    cudaGetSymbolAddress((void**)&W2h,    g_W2h);

    static cudaStream_t s2 = nullptr;
    static cudaEvent_t evFork = nullptr, evJoin = nullptr;
    if (!s2) {
        cudaStreamCreateWithFlags(&s2, cudaStreamNonBlocking);
        cudaEventCreateWithFlags(&evFork, cudaEventDisableTiming);
        cudaEventCreateWithFlags(&evJoin, cudaEventDisableTiming);
    }

    cudaFuncSetAttribute(gemm_tc_f32,
                         cudaFuncAttributeMaxDynamicSharedMemorySize, GEMM_SMEM);
    cudaFuncSetAttribute(gemm_tc_f16,
                         cudaFuncAttributeMaxDynamicSharedMemorySize, GEMM_SMEM);

    const int warpGrid = (NN * 32 + 255) / 256;
    const int gemmGrid = (NN + BM - 1) / BM;
    const int eGrid    = (NEDGT + 255) / 256;

    // Fork: padded-CSR build + W2 pre-convert + weff concurrent with GEMM1
    cudaEventRecord(evFork, 0);
    cudaStreamWaitEvent(s2, evFork, 0);

    csr_build_kernel<<<eGrid, 256, 0, s2>>>(esrc, edst);
    wconv_kernel<<<16, 256, 0, s2>>>(W2, W2h);
    weff_kernel<<<1, 128, 0, s2>>>(Wc1, bc1, Wc2, bc2);
    cudaEventRecord(evJoin, s2);            // CSR + W2h + weff ready

    // Layer 1: TC GEMM + alphas fused
    gemm_tc_f32<<<gemmGrid, 256, GEMM_SMEM>>>(x, W1, as1, ad1, h16, NN);

    cudaStreamWaitEvent(0, evJoin, 0);
    agg_fused_kernel<<<warpGrid, 256>>>(h16, b1, feat16);

    // Layer 2 (fp16 input, pre-converted fp16 W)
    gemm_tc_f16<<<gemmGrid, 256, GEMM_SMEM>>>(feat16, W2h, as2, ad2, h16, NN);
    agg_final_kernel<<<warpGrid, 256>>>(h16, b2, out);
}